// round 1
// baseline (speedup 1.0000x reference)
#include <cuda_runtime.h>
#include <cstdint>

#define BDIM 64
#define TDIM 512
#define IDIM 1024
#define HDIM 1024
#define BT   (BDIM * TDIM)      // 32768

// ---------------- scratch (static device memory; no allocations) ----------------
__device__ float g_pre[3][(size_t)BT * HDIM];   // 3 x 128MB pre-activations
__device__ float g_xr[(size_t)BT * IDIM];       // tf32-rounded x
__device__ float g_wr[3][(size_t)HDIM * IDIM];  // tf32-rounded W_f, W_i, W_g
__device__ float g_hr[3][BDIM * HDIM];          // h0@R.T + b + rb per gate

__device__ __forceinline__ float to_tf32(float x) {
    uint32_t u;
    asm("cvt.rna.tf32.f32 %0, %1;" : "=r"(u) : "f"(x));
    return __uint_as_float(u);
}

// ---------------- pre-round kernels ----------------
__global__ void round_x_kernel(const float* __restrict__ x) {
    size_t i = (size_t)blockIdx.x * blockDim.x + threadIdx.x;   // float4 index
    const float4* src = (const float4*)x;
    float4* dst = (float4*)g_xr;
    float4 v = src[i];
    v.x = to_tf32(v.x); v.y = to_tf32(v.y); v.z = to_tf32(v.z); v.w = to_tf32(v.w);
    dst[i] = v;
}

__global__ void round_w_kernel(const float* __restrict__ Wf,
                               const float* __restrict__ Wi,
                               const float* __restrict__ Wg) {
    const size_t HI4 = (size_t)HDIM * IDIM / 4;
    size_t i = (size_t)blockIdx.x * blockDim.x + threadIdx.x;   // float4 index over 3*H*I
    int g = (int)(i / HI4);
    size_t l = i - (size_t)g * HI4;
    const float4* src = (const float4*)(g == 0 ? Wf : (g == 1 ? Wi : Wg));
    float4* dst = (float4*)g_wr[g];
    float4 v = src[l];
    v.x = to_tf32(v.x); v.y = to_tf32(v.y); v.z = to_tf32(v.z); v.w = to_tf32(v.w);
    dst[l] = v;
}

// ---------------- recurrent part: hr[g][b][h] = h0[b]·R_g[h] + b_g[h] + rb_g[h] ----------------
__global__ void hr_kernel(const float* __restrict__ h0,
                          const float* __restrict__ Rf, const float* __restrict__ bf, const float* __restrict__ rbf,
                          const float* __restrict__ Ri, const float* __restrict__ bi, const float* __restrict__ rbi,
                          const float* __restrict__ Rg, const float* __restrict__ bg, const float* __restrict__ rbg) {
    int w = blockIdx.x * (blockDim.x >> 5) + (threadIdx.x >> 5);
    int lane = threadIdx.x & 31;
    int g = w >> 16;              // / (64*1024)
    int rem = w & 65535;
    int b = rem >> 10;
    int h = rem & 1023;
    const float* R; const float* bb; const float* rb;
    if (g == 0)      { R = Rf; bb = bf; rb = rbf; }
    else if (g == 1) { R = Ri; bb = bi; rb = rbi; }
    else             { R = Rg; bb = bg; rb = rbg; }

    const float4* h4 = (const float4*)(h0 + (size_t)b * HDIM);
    const float4* R4 = (const float4*)(R + (size_t)h * HDIM);
    float s = 0.f;
    #pragma unroll
    for (int k = lane; k < HDIM / 4; k += 32) {
        float4 a = h4[k], r = R4[k];
        s += a.x * r.x + a.y * r.y + a.z * r.z + a.w * r.w;
    }
    #pragma unroll
    for (int off = 16; off; off >>= 1) s += __shfl_xor_sync(0xffffffffu, s, off);
    if (lane == 0) g_hr[g][rem] = s + bb[h] + rb[h];
}

// ---------------- TF32 GEMM: C[m,n] = sum_k A[m,k] * W[n,k] ----------------
#define GBM 128
#define GBN 128
#define GBK 32
#define GSTAGES 3
#define GPAD 4
#define GROWSZ (GBK + GPAD)          // 36 floats per smem row
#define ASTAGE (GBM * GROWSZ)        // floats per stage per operand
#define GSMEM_BYTES (GSTAGES * ASTAGE * 2 * 4)   // 110592

__device__ __forceinline__ void mma_tf32(float c[4], const uint32_t a[4], const uint32_t b[2]) {
    asm volatile(
        "mma.sync.aligned.m16n8k8.row.col.f32.tf32.tf32.f32 "
        "{%0,%1,%2,%3}, {%4,%5,%6,%7}, {%8,%9}, {%0,%1,%2,%3};\n"
        : "+f"(c[0]), "+f"(c[1]), "+f"(c[2]), "+f"(c[3])
        : "r"(a[0]), "r"(a[1]), "r"(a[2]), "r"(a[3]), "r"(b[0]), "r"(b[1]));
}

__global__ __launch_bounds__(256)
void gemm_tf32(int gate) {
    extern __shared__ float sm[];
    float* As = sm;
    float* Bs = sm + GSTAGES * ASTAGE;

    const float* __restrict__ A  = g_xr;
    const float* __restrict__ Bw = g_wr[gate];
    float* __restrict__ C = g_pre[gate];

    const int tid  = threadIdx.x;
    const int lane = tid & 31;
    const int warp = tid >> 5;
    const int wm = (warp & 3) * 32;      // warp m-offset within block tile
    const int wn = (warp >> 2) * 64;     // warp n-offset
    const int bm = blockIdx.x * GBM;
    const int bn = blockIdx.y * GBN;

    // global -> smem mapping: 256 threads, each 4 x float4 per operand per stage
    const int lr = tid >> 3;             // 0..31 (row group)
    const int lc = (tid & 7) * 4;        // float column 0,4,..,28
    const float* Ag = A  + (size_t)(bm + lr) * IDIM + lc;
    const float* Bg = Bw + (size_t)(bn + lr) * IDIM + lc;

    // ldmatrix per-lane offsets
    const int r8 = lane & 7;
    const int q  = lane >> 3;
    const int a_row = (q & 1) * 8 + r8;  // within 16-row m-tile
    const int a_col = (q >> 1) * 4;      // 0 or 4
    const int b_row = (q >> 1) * 8 + r8; // within 16-row n-pair
    const int b_col = (q & 1) * 4;       // 0 or 4

    float acc[2][8][4];
    #pragma unroll
    for (int mt = 0; mt < 2; mt++)
        #pragma unroll
        for (int j = 0; j < 8; j++)
            #pragma unroll
            for (int v = 0; v < 4; v++) acc[mt][j][v] = 0.f;

    auto load_stage = [&](int stage, int k0) {
        float* as = As + stage * ASTAGE;
        float* bs = Bs + stage * ASTAGE;
        #pragma unroll
        for (int i = 0; i < 4; i++) {
            uint32_t da = (uint32_t)__cvta_generic_to_shared(&as[(lr + i * 32) * GROWSZ + lc]);
            asm volatile("cp.async.cg.shared.global [%0], [%1], 16;\n"
                         :: "r"(da), "l"(Ag + (size_t)i * 32 * IDIM + k0));
            uint32_t db = (uint32_t)__cvta_generic_to_shared(&bs[(lr + i * 32) * GROWSZ + lc]);
            asm volatile("cp.async.cg.shared.global [%0], [%1], 16;\n"
                         :: "r"(db), "l"(Bg + (size_t)i * 32 * IDIM + k0));
        }
        asm volatile("cp.async.commit_group;\n");
    };

    #pragma unroll
    for (int s = 0; s < GSTAGES - 1; s++) load_stage(s, s * GBK);

    const int ktiles = IDIM / GBK;   // 32
    for (int kt = 0; kt < ktiles; kt++) {
        asm volatile("cp.async.wait_group %0;\n" :: "n"(GSTAGES - 2));
        __syncthreads();
        const int cur = kt % GSTAGES;
        if (kt + GSTAGES - 1 < ktiles)
            load_stage((kt + GSTAGES - 1) % GSTAGES, (kt + GSTAGES - 1) * GBK);

        const float* as = As + cur * ASTAGE;
        const float* bs = Bs + cur * ASTAGE;

        #pragma unroll
        for (int ks = 0; ks < GBK / 8; ks++) {
            const int k0 = ks * 8;
            uint32_t afr[2][4], bfr[8][2];
            #pragma unroll
            for (int mt = 0; mt < 2; mt++) {
                uint32_t addr = (uint32_t)__cvta_generic_to_shared(
                    &as[(wm + mt * 16 + a_row) * GROWSZ + k0 + a_col]);
                asm volatile("ldmatrix.sync.aligned.m8n8.x4.shared.b16 {%0,%1,%2,%3}, [%4];\n"
                             : "=r"(afr[mt][0]), "=r"(afr[mt][1]), "=r"(afr[mt][2]), "=r"(afr[mt][3])
                             : "r"(addr));
            }
            #pragma unroll
            for (int j2 = 0; j2 < 4; j2++) {
                uint32_t addr = (uint32_t)__cvta_generic_to_shared(
                    &bs[(wn + j2 * 16 + b_row) * GROWSZ + k0 + b_col]);
                uint32_t d0, d1, d2, d3;
                asm volatile("ldmatrix.sync.aligned.m8n8.x4.shared.b16 {%0,%1,%2,%3}, [%4];\n"
                             : "=r"(d0), "=r"(d1), "=r"(d2), "=r"(d3) : "r"(addr));
                bfr[2 * j2][0] = d0; bfr[2 * j2][1] = d1;
                bfr[2 * j2 + 1][0] = d2; bfr[2 * j2 + 1][1] = d3;
            }
            #pragma unroll
            for (int mt = 0; mt < 2; mt++)
                #pragma unroll
                for (int j = 0; j < 8; j++)
                    mma_tf32(acc[mt][j], afr[mt], bfr[j]);
        }
    }

    // writeback
    const int tig = lane & 3, grp = lane >> 2;
    #pragma unroll
    for (int mt = 0; mt < 2; mt++) {
        const int row0 = bm + wm + mt * 16 + grp;
        #pragma unroll
        for (int j = 0; j < 8; j++) {
            const int col = bn + wn + j * 8 + tig * 2;
            *(float2*)&C[(size_t)row0 * HDIM + col]       = make_float2(acc[mt][j][0], acc[mt][j][1]);
            *(float2*)&C[(size_t)(row0 + 8) * HDIM + col] = make_float2(acc[mt][j][2], acc[mt][j][3]);
        }
    }
}

// ---------------- epilogue: gates, cell, tanh, transposed store ----------------
__device__ __forceinline__ float sigmoid_f(float x) { return 1.f / (1.f + __expf(-x)); }
__device__ __forceinline__ float tanh_f(float x)    { return 2.f / (1.f + __expf(-2.f * x)) - 1.f; }

__global__ void epilogue_kernel(const float* __restrict__ c0, float* __restrict__ out, int write_last) {
    __shared__ float tile[32][65];
    const int t = blockIdx.y;
    const int hbase = blockIdx.x * 32;
    const int tid = threadIdx.x;
    const int h_r = tid & 31, b_r = tid >> 5;

    float* hlast = out + (size_t)HDIM * TDIM * BDIM;
    float* clast = hlast + (size_t)BDIM * HDIM;

    #pragma unroll
    for (int bi = 0; bi < 8; bi++) {
        const int b = bi * 8 + b_r;
        const int h = hbase + h_r;
        const size_t m = (size_t)b * TDIM + t;
        const size_t idx = m * HDIM + h;
        const int bh = b * HDIM + h;
        float pf = g_pre[0][idx] + g_hr[0][bh];
        float pi = g_pre[1][idx] + g_hr[1][bh];
        float pg = g_pre[2][idx] + g_hr[2][bh];
        float f  = sigmoid_f(pf);
        float ii = sigmoid_f(pi);
        float gg = tanh_f(pg);
        float c  = f * c0[bh] + ii * gg;
        float hh = tanh_f(c);
        tile[h_r][b] = hh;
        if (write_last && t == TDIM - 1) { hlast[bh] = hh; clast[bh] = c; }
    }
    __syncthreads();
    const int b_w = tid & 63, h_w = tid >> 6;
    #pragma unroll
    for (int hi = 0; hi < 8; hi++) {
        const int h = hi * 4 + h_w;
        out[(size_t)(hbase + h) * (TDIM * BDIM) + (size_t)t * BDIM + b_w] = tile[h][b_w];
    }
}

// ---------------- launch ----------------
extern "C" void kernel_launch(void* const* d_in, const int* in_sizes, int n_in,
                              void* d_out, int out_size) {
    const float* x   = (const float*)d_in[0];
    const float* h0  = (const float*)d_in[1];
    const float* c0  = (const float*)d_in[2];
    const float* Wf  = (const float*)d_in[3];
    const float* bf  = (const float*)d_in[4];
    const float* Rf  = (const float*)d_in[5];
    const float* rbf = (const float*)d_in[6];
    const float* Wi  = (const float*)d_in[7];
    const float* bi  = (const float*)d_in[8];
    const float* Ri  = (const float*)d_in[9];
    const float* rbi = (const float*)d_in[10];
    const float* Wg  = (const float*)d_in[11];
    const float* bg  = (const float*)d_in[12];
    const float* Rg  = (const float*)d_in[13];
    const float* rbg = (const float*)d_in[14];
    float* out = (float*)d_out;

    cudaFuncSetAttribute(gemm_tf32, cudaFuncAttributeMaxDynamicSharedMemorySize, GSMEM_BYTES);

    // pre-round inputs to tf32
    round_x_kernel<<<(BT * IDIM / 4) / 256, 256>>>(x);
    round_w_kernel<<<(3 * HDIM * IDIM / 4) / 256, 256>>>(Wf, Wi, Wg);

    // recurrent contribution (+ biases)
    hr_kernel<<<(3 * BDIM * HDIM) / 8, 256>>>(h0, Rf, bf, rbf, Ri, bi, rbi, Rg, bg, rbg);

    // three big GEMMs
    dim3 ggrid(BT / GBM, HDIM / GBN);
    for (int g = 0; g < 3; g++)
        gemm_tf32<<<ggrid, 256, GSMEM_BYTES>>>(g);

    // fused activation + transpose epilogue
    const long long need = (long long)HDIM * TDIM * BDIM + 2LL * BDIM * HDIM;
    int write_last = ((long long)out_size >= need) ? 1 : 0;
    epilogue_kernel<<<dim3(HDIM / 32, TDIM), 256>>>(c0, out, write_last);
}

// round 6
// speedup vs baseline: 1.1981x; 1.1981x over previous
#include <cuda_runtime.h>
#include <cuda_fp16.h>
#include <cstdint>

#define BDIM 64
#define TDIM 512
#define IDIM 1024
#define HDIM 1024
#define BT   (BDIM * TDIM)      // 32768

#define BM 128                  // M tile (rows m' = t*B+b)
#define BGN 64                  // N tile per gate
#define BN3 192                 // 3 gates packed
#define BK 64                   // K per chunk (halves) = 128B rows
#define NCH (IDIM / BK)         // 16 chunks
#define RP 72                   // smem row pitch in halves (BK + 8)
#define A_H (BM * RP)           // 9216 halves per A stage
#define B_H (BN3 * RP)          // 13824 halves per B stage
#define STG_B ((A_H + B_H) * 2) // 46080 bytes per stage
#define NST 3
#define SMEM_DYN (NST * STG_B)  // 138240

// ---------------- scratch ----------------
__device__ __half g_xh[(size_t)BT * IDIM];          // fp16 x, remapped m' = t*B+b
__device__ __half g_wh[(size_t)3 * HDIM * IDIM];    // fp16 W packed [nt][3*64][IDIM]
__device__ float  g_hr[3][BDIM * HDIM];             // h0@R.T + b + rb per gate

// ---------------- helpers ----------------
__device__ __forceinline__ uint32_t smem_u32(const void* p) {
    uint32_t a;
    asm("{ .reg .u64 t; cvta.to.shared.u64 t, %1; cvt.u32.u64 %0, t; }" : "=r"(a) : "l"(p));
    return a;
}
#define LDMX4(r, addr) \
    asm volatile("ldmatrix.sync.aligned.m8n8.x4.shared.b16 {%0,%1,%2,%3}, [%4];\n" \
        : "=r"((r)[0]), "=r"((r)[1]), "=r"((r)[2]), "=r"((r)[3]) : "r"(addr))

__device__ __forceinline__ void mma16816(float* c, const uint32_t* a, const uint32_t* b) {
    asm volatile(
        "mma.sync.aligned.m16n8k16.row.col.f32.f16.f16.f32 "
        "{%0,%1,%2,%3}, {%4,%5,%6,%7}, {%8,%9}, {%0,%1,%2,%3};\n"
        : "+f"(c[0]), "+f"(c[1]), "+f"(c[2]), "+f"(c[3])
        : "r"(a[0]), "r"(a[1]), "r"(a[2]), "r"(a[3]), "r"(b[0]), "r"(b[1]));
}

__device__ __forceinline__ float sigmoid_f(float x) { return 1.f / (1.f + __expf(-x)); }
__device__ __forceinline__ float tanh_f(float x)    { return 2.f / (1.f + __expf(-2.f * x)) - 1.f; }

// ---------------- conversion kernels ----------------
// g_xh[m'][k] = fp16(x[b][t][k]),  m' = t*B + b
__global__ void conv_x(const float* __restrict__ x) {
    size_t i = (size_t)blockIdx.x * blockDim.x + threadIdx.x;  // 8-half group
    int m = (int)(i >> 7);
    int c8 = (int)(i & 127) * 8;
    int b = m & 63, t = m >> 6;
    const float4* s = (const float4*)(x + ((size_t)b * TDIM + t) * IDIM + c8);
    float4 v0 = s[0], v1 = s[1];
    union { __half2 h[4]; uint4 u; } r;
    r.h[0] = __floats2half2_rn(v0.x, v0.y);
    r.h[1] = __floats2half2_rn(v0.z, v0.w);
    r.h[2] = __floats2half2_rn(v1.x, v1.y);
    r.h[3] = __floats2half2_rn(v1.z, v1.w);
    *(uint4*)(g_xh + (size_t)m * IDIM + c8) = r.u;
}

// packed weights: prow = nt*192 + g*64 + (h&63) for h = nt*64 + (h&63)
__global__ void conv_w(const float* __restrict__ Wf,
                       const float* __restrict__ Wi,
                       const float* __restrict__ Wg) {
    size_t i = (size_t)blockIdx.x * blockDim.x + threadIdx.x;  // 8-half group
    int prow = (int)(i >> 7);
    int c8 = (int)(i & 127) * 8;
    int nt = prow / BN3, r = prow % BN3;
    int g = r >> 6, hl = r & 63;
    int h = nt * 64 + hl;
    const float* W = (g == 0) ? Wf : ((g == 1) ? Wi : Wg);
    const float4* s = (const float4*)(W + (size_t)h * IDIM + c8);
    float4 v0 = s[0], v1 = s[1];
    union { __half2 h2[4]; uint4 u; } rr;
    rr.h2[0] = __floats2half2_rn(v0.x, v0.y);
    rr.h2[1] = __floats2half2_rn(v0.z, v0.w);
    rr.h2[2] = __floats2half2_rn(v1.x, v1.y);
    rr.h2[3] = __floats2half2_rn(v1.z, v1.w);
    *(uint4*)(g_wh + (size_t)prow * IDIM + c8) = rr.u;
}

// ---------------- recurrent part (fp32) ----------------
__global__ void hr_kernel(const float* __restrict__ h0,
                          const float* __restrict__ Rf, const float* __restrict__ bf, const float* __restrict__ rbf,
                          const float* __restrict__ Ri, const float* __restrict__ bi, const float* __restrict__ rbi,
                          const float* __restrict__ Rg, const float* __restrict__ bg, const float* __restrict__ rbg) {
    int w = blockIdx.x * (blockDim.x >> 5) + (threadIdx.x >> 5);
    int lane = threadIdx.x & 31;
    int g = w >> 16;
    int rem = w & 65535;
    int b = rem >> 10;
    int h = rem & 1023;
    const float* R; const float* bb; const float* rb;
    if (g == 0)      { R = Rf; bb = bf; rb = rbf; }
    else if (g == 1) { R = Ri; bb = bi; rb = rbi; }
    else             { R = Rg; bb = bg; rb = rbg; }

    const float4* h4 = (const float4*)(h0 + (size_t)b * HDIM);
    const float4* R4 = (const float4*)(R + (size_t)h * HDIM);
    float s = 0.f;
    #pragma unroll
    for (int k = lane; k < HDIM / 4; k += 32) {
        float4 a = h4[k], r = R4[k];
        s += a.x * r.x + a.y * r.y + a.z * r.z + a.w * r.w;
    }
    #pragma unroll
    for (int off = 16; off; off >>= 1) s += __shfl_xor_sync(0xffffffffu, s, off);
    if (lane == 0) g_hr[g][rem] = s + bb[h] + rb[h];
}

// ---------------- fused 3-gate FP16 GEMM + LSTM epilogue ----------------
__global__ __launch_bounds__(256)
void lstm_fused(const float* __restrict__ c0, float* __restrict__ out, int write_last) {
    extern __shared__ char dsm[];
    const uint32_t base = smem_u32(dsm);

    const int tid = threadIdx.x, lane = tid & 31, warp = tid >> 5;
    const int wm = (warp & 3) * 32;       // warp m offset in 128
    const int wn = (warp >> 2) * 32;      // warp n offset in 64 (per gate)
    const int nt = blockIdx.x;            // 0..15 (h block of 64)
    const int m0 = blockIdx.y * BM;       // m' offset
    const int n0 = nt * 64;

    // global load pointers (per thread, 16B granules)
    const int lr = tid >> 3;              // 0..31
    const int lc = (tid & 7) * 8;         // half column
    const __half* gA = g_xh + (size_t)(m0 + lr) * IDIM + lc;
    const __half* gB = g_wh + (size_t)(nt * BN3 + lr) * IDIM + lc;
    const uint32_t sA = base + (uint32_t)(lr * RP + lc) * 2;
    const uint32_t sB = base + (uint32_t)(A_H + lr * RP + lc) * 2;

    float acc[3][2][4][4];
    #pragma unroll
    for (int g = 0; g < 3; g++)
        #pragma unroll
        for (int mt = 0; mt < 2; mt++)
            #pragma unroll
            for (int j = 0; j < 4; j++)
                #pragma unroll
                for (int v = 0; v < 4; v++) acc[g][mt][j][v] = 0.f;

    auto load_stage = [&](int stage, int ch) {
        const uint32_t off = stage * STG_B;
        const __half* a = gA + ch * BK;
        const __half* b = gB + ch * BK;
        #pragma unroll
        for (int i = 0; i < 4; i++)
            asm volatile("cp.async.cg.shared.global [%0], [%1], 16;\n"
                         :: "r"(sA + off + i * 32 * RP * 2), "l"(a + (size_t)i * 32 * IDIM));
        #pragma unroll
        for (int i = 0; i < 6; i++)
            asm volatile("cp.async.cg.shared.global [%0], [%1], 16;\n"
                         :: "r"(sB + off + i * 32 * RP * 2), "l"(b + (size_t)i * 32 * IDIM));
        asm volatile("cp.async.commit_group;\n");
    };

    load_stage(0, 0);
    load_stage(1, 1);

    // ldmatrix lane offsets
    const int a_row = lane & 15;
    const int a_k8  = (lane >> 4) * 8;                    // halves
    const int b_row = (lane & 7) + ((lane >> 4) << 3);    // n within 16
    const int b_k8  = ((lane >> 3) & 1) * 8;              // halves

    for (int kt = 0; kt < NCH; kt++) {
        asm volatile("cp.async.wait_group %0;\n" :: "n"(NST - 2));
        __syncthreads();
        const int cur = kt % NST;
        if (kt + 2 < NCH) load_stage((kt + 2) % NST, kt + 2);

        const uint32_t aB = base + cur * STG_B;
        const uint32_t bB = aB + A_H * 2;

        #pragma unroll
        for (int ks = 0; ks < BK / 16; ks++) {
            uint32_t afr[2][4];
            #pragma unroll
            for (int mt = 0; mt < 2; mt++)
                LDMX4(afr[mt], aB + (uint32_t)((wm + mt * 16 + a_row) * RP + ks * 16 + a_k8) * 2);

            uint32_t bfr[2][4][2];
            // load gate 0
            #pragma unroll
            for (int nt2 = 0; nt2 < 2; nt2++) {
                uint32_t r[4];
                LDMX4(r, bB + (uint32_t)((0 * 64 + wn + nt2 * 16 + b_row) * RP + ks * 16 + b_k8) * 2);
                bfr[0][nt2 * 2][0] = r[0]; bfr[0][nt2 * 2][1] = r[1];
                bfr[0][nt2 * 2 + 1][0] = r[2]; bfr[0][nt2 * 2 + 1][1] = r[3];
            }
            #pragma unroll
            for (int g = 0; g < 3; g++) {
                if (g < 2) {
                    #pragma unroll
                    for (int nt2 = 0; nt2 < 2; nt2++) {
                        uint32_t r[4];
                        LDMX4(r, bB + (uint32_t)(((g + 1) * 64 + wn + nt2 * 16 + b_row) * RP + ks * 16 + b_k8) * 2);
                        bfr[(g + 1) & 1][nt2 * 2][0] = r[0]; bfr[(g + 1) & 1][nt2 * 2][1] = r[1];
                        bfr[(g + 1) & 1][nt2 * 2 + 1][0] = r[2]; bfr[(g + 1) & 1][nt2 * 2 + 1][1] = r[3];
                    }
                }
                #pragma unroll
                for (int mt = 0; mt < 2; mt++)
                    #pragma unroll
                    for (int j = 0; j < 4; j++)
                        mma16816(acc[g][mt][j], afr[mt], bfr[g & 1][j]);
            }
        }
    }
    __syncthreads();   // done with smem tiles; reuse for transpose staging

    // ---- epilogue: gates + cell + tanh, staged transpose ----
    float* trans = (float*)dsm;          // [64][132]
    float* hlast = out + (size_t)HDIM * BT;
    float* clast = hlast + (size_t)BDIM * HDIM;
    const int grp = lane >> 2, tig = lane & 3;

    #pragma unroll
    for (int mt = 0; mt < 2; mt++) {
        #pragma unroll
        for (int j = 0; j < 4; j++) {
            #pragma unroll
            for (int v = 0; v < 4; v++) {
                const int m_l = wm + mt * 16 + grp + ((v >> 1) << 3);
                const int h_l = wn + j * 8 + tig * 2 + (v & 1);
                const int mg = m0 + m_l;
                const int b = mg & 63, t = mg >> 6;
                const int h = n0 + h_l;
                const int bh = (b << 10) + h;
                const float pf = acc[0][mt][j][v] + g_hr[0][bh];
                const float pi = acc[1][mt][j][v] + g_hr[1][bh];
                const float pg = acc[2][mt][j][v] + g_hr[2][bh];
                const float f  = sigmoid_f(pf);
                const float ii = sigmoid_f(pi);
                const float gg = tanh_f(pg);
                const float cv = f * c0[bh] + ii * gg;
                const float hh = tanh_f(cv);
                trans[h_l * 132 + m_l] = hh;
                if (write_last && t == TDIM - 1) { hlast[bh] = hh; clast[bh] = cv; }
            }
        }
    }
    __syncthreads();
    #pragma unroll
    for (int idx = tid; idx < 64 * 128; idx += 256) {
        const int h = idx >> 7, m = idx & 127;
        out[(size_t)(n0 + h) * BT + (m0 + m)] = trans[h * 132 + m];
    }
}

// ---------------- launch ----------------
extern "C" void kernel_launch(void* const* d_in, const int* in_sizes, int n_in,
                              void* d_out, int out_size) {
    const float* x   = (const float*)d_in[0];
    const float* h0  = (const float*)d_in[1];
    const float* c0  = (const float*)d_in[2];
    const float* Wf  = (const float*)d_in[3];
    const float* bf  = (const float*)d_in[4];
    const float* Rf  = (const float*)d_in[5];
    const float* rbf = (const float*)d_in[6];
    const float* Wi  = (const float*)d_in[7];
    const float* bi  = (const float*)d_in[8];
    const float* Ri  = (const float*)d_in[9];
    const float* rbi = (const float*)d_in[10];
    const float* Wg  = (const float*)d_in[11];
    const float* bg  = (const float*)d_in[12];
    const float* Rg  = (const float*)d_in[13];
    const float* rbg = (const float*)d_in[14];
    float* out = (float*)d_out;

    cudaFuncSetAttribute(lstm_fused, cudaFuncAttributeMaxDynamicSharedMemorySize, SMEM_DYN);

    // convert inputs to fp16 (x remapped to m'=t*B+b; W packed per n-tile)
    conv_x<<<(int)(((size_t)BT * IDIM / 8) / 256), 256>>>(x);
    conv_w<<<(int)(((size_t)3 * HDIM * IDIM / 8) / 256), 256>>>(Wf, Wi, Wg);

    // recurrent contribution (+ biases), fp32
    hr_kernel<<<(3 * BDIM * HDIM) / 8, 256>>>(h0, Rf, bf, rbf, Ri, bi, rbi, Rg, bg, rbg);

    // fused 3-gate GEMM + epilogue
    const long long need = (long long)HDIM * BT + 2LL * BDIM * HDIM;
    int write_last = ((long long)out_size >= need) ? 1 : 0;
    dim3 grid(HDIM / 64, BT / BM);   // (16, 256); x-fast => A tile reused across n-blocks in L2
    lstm_fused<<<grid, 256, SMEM_DYN>>>(c0, out, write_last);
}

// round 11
// speedup vs baseline: 1.5468x; 1.2911x over previous
#include <cuda_runtime.h>
#include <cuda_fp16.h>
#include <cstdint>

#define BDIM 64
#define TDIM 512
#define IDIM 1024
#define HDIM 1024
#define BT   (BDIM * TDIM)      // 32768

#define BM 128                  // M tile (rows m' = t*B+b)
#define BN3 192                 // 3 gates x 64
#define BK 32                   // K per chunk (halves) = 64B rows
#define NCH (IDIM / BK)         // 32 chunks
#define RP 40                   // smem row pitch in halves (80B, conflict-free mod 32 banks)
#define A_H (BM * RP)           // 5120 halves per A stage
#define B_H (BN3 * RP)          // 7680 halves per B stage
#define STG_B ((A_H + B_H) * 2) // 25600 bytes per stage
#define NST 4
#define SMEM_DYN (NST * STG_B)  // 102400 -> 2 CTAs/SM

// ---------------- scratch ----------------
__device__ __half g_xh[(size_t)BT * IDIM];          // fp16 x, remapped m' = t*B+b
__device__ __half g_wh[(size_t)3 * HDIM * IDIM];    // fp16 W packed [nt][3*64][IDIM]
__device__ float  g_hr[3][BDIM * HDIM];             // h0@R.T + b + rb per gate

// ---------------- helpers ----------------
__device__ __forceinline__ uint32_t smem_u32(const void* p) {
    uint32_t a;
    asm("{ .reg .u64 t; cvta.to.shared.u64 t, %1; cvt.u32.u64 %0, t; }" : "=r"(a) : "l"(p));
    return a;
}
#define LDMX4(r, addr) \
    asm volatile("ldmatrix.sync.aligned.m8n8.x4.shared.b16 {%0,%1,%2,%3}, [%4];\n" \
        : "=r"((r)[0]), "=r"((r)[1]), "=r"((r)[2]), "=r"((r)[3]) : "r"(addr))

__device__ __forceinline__ void mma16816(float* c, const uint32_t* a, const uint32_t* b) {
    asm volatile(
        "mma.sync.aligned.m16n8k16.row.col.f32.f16.f16.f32 "
        "{%0,%1,%2,%3}, {%4,%5,%6,%7}, {%8,%9}, {%0,%1,%2,%3};\n"
        : "+f"(c[0]), "+f"(c[1]), "+f"(c[2]), "+f"(c[3])
        : "r"(a[0]), "r"(a[1]), "r"(a[2]), "r"(a[3]), "r"(b[0]), "r"(b[1]));
}

__device__ __forceinline__ float sigmoid_f(float x) { return 1.f / (1.f + __expf(-x)); }
__device__ __forceinline__ float tanh_f(float x)    { return 2.f / (1.f + __expf(-2.f * x)) - 1.f; }

// ---------------- conversion kernels ----------------
// g_xh[m'][k] = fp16(x[b][t][k]),  m' = t*B + b
__global__ void conv_x(const float* __restrict__ x) {
    size_t i = (size_t)blockIdx.x * blockDim.x + threadIdx.x;  // 8-half group
    int m = (int)(i >> 7);
    int c8 = (int)(i & 127) * 8;
    int b = m & 63, t = m >> 6;
    const float4* s = (const float4*)(x + ((size_t)b * TDIM + t) * IDIM + c8);
    float4 v0 = s[0], v1 = s[1];
    union { __half2 h[4]; uint4 u; } r;
    r.h[0] = __floats2half2_rn(v0.x, v0.y);
    r.h[1] = __floats2half2_rn(v0.z, v0.w);
    r.h[2] = __floats2half2_rn(v1.x, v1.y);
    r.h[3] = __floats2half2_rn(v1.z, v1.w);
    *(uint4*)(g_xh + (size_t)m * IDIM + c8) = r.u;
}

// packed weights: prow = nt*192 + g*64 + (h&63) for h = nt*64 + (h&63)
__global__ void conv_w(const float* __restrict__ Wf,
                       const float* __restrict__ Wi,
                       const float* __restrict__ Wg) {
    size_t i = (size_t)blockIdx.x * blockDim.x + threadIdx.x;  // 8-half group
    int prow = (int)(i >> 7);
    int c8 = (int)(i & 127) * 8;
    int nt = prow / BN3, r = prow % BN3;
    int g = r >> 6, hl = r & 63;
    int h = nt * 64 + hl;
    const float* W = (g == 0) ? Wf : ((g == 1) ? Wi : Wg);
    const float4* s = (const float4*)(W + (size_t)h * IDIM + c8);
    float4 v0 = s[0], v1 = s[1];
    union { __half2 h2[4]; uint4 u; } rr;
    rr.h2[0] = __floats2half2_rn(v0.x, v0.y);
    rr.h2[1] = __floats2half2_rn(v0.z, v0.w);
    rr.h2[2] = __floats2half2_rn(v1.x, v1.y);
    rr.h2[3] = __floats2half2_rn(v1.z, v1.w);
    *(uint4*)(g_wh + (size_t)prow * IDIM + c8) = rr.u;
}

// ---------------- recurrent part (fp32) ----------------
__global__ void hr_kernel(const float* __restrict__ h0,
                          const float* __restrict__ Rf, const float* __restrict__ bf, const float* __restrict__ rbf,
                          const float* __restrict__ Ri, const float* __restrict__ bi, const float* __restrict__ rbi,
                          const float* __restrict__ Rg, const float* __restrict__ bg, const float* __restrict__ rbg) {
    int w = blockIdx.x * (blockDim.x >> 5) + (threadIdx.x >> 5);
    int lane = threadIdx.x & 31;
    int g = w >> 16;
    int rem = w & 65535;
    int b = rem >> 10;
    int h = rem & 1023;
    const float* R; const float* bb; const float* rb;
    if (g == 0)      { R = Rf; bb = bf; rb = rbf; }
    else if (g == 1) { R = Ri; bb = bi; rb = rbi; }
    else             { R = Rg; bb = bg; rb = rbg; }

    const float4* h4 = (const float4*)(h0 + (size_t)b * HDIM);
    const float4* R4 = (const float4*)(R + (size_t)h * HDIM);
    float s = 0.f;
    #pragma unroll
    for (int k = lane; k < HDIM / 4; k += 32) {
        float4 a = h4[k], r = R4[k];
        s += a.x * r.x + a.y * r.y + a.z * r.z + a.w * r.w;
    }
    #pragma unroll
    for (int off = 16; off; off >>= 1) s += __shfl_xor_sync(0xffffffffu, s, off);
    if (lane == 0) g_hr[g][rem] = s + bb[h] + rb[h];
}

// ---------------- fused 3-gate FP16 GEMM + LSTM epilogue ----------------
__global__ __launch_bounds__(256, 2)
void lstm_fused(const float* __restrict__ c0, float* __restrict__ out, int write_last) {
    extern __shared__ char dsm[];
    const uint32_t base = smem_u32(dsm);

    const int tid = threadIdx.x, lane = tid & 31, warp = tid >> 5;
    const int wm = (warp & 3) * 32;       // warp m offset in 128
    const int wn = (warp >> 2) * 32;      // warp n offset in 64 (per gate)
    const int nt = blockIdx.x;            // 0..15 (h block of 64)
    const int m0 = blockIdx.y * BM;       // m' offset
    const int n0 = nt * 64;

    // cp.async mapping: 16B granules; per row 32 halves = 4 granules
    const int cr = tid >> 2;              // row 0..63
    const int cg = (tid & 3) * 8;         // half col within chunk
    const __half* gA = g_xh + (size_t)(m0 + cr) * IDIM + cg;
    const __half* gB = g_wh + (size_t)(nt * BN3 + cr) * IDIM + cg;
    const uint32_t sA = base + (uint32_t)(cr * RP + cg) * 2;
    const uint32_t sB = base + (uint32_t)(A_H + cr * RP + cg) * 2;

    float acc[3][2][4][4];
    #pragma unroll
    for (int g = 0; g < 3; g++)
        #pragma unroll
        for (int mt = 0; mt < 2; mt++)
            #pragma unroll
            for (int j = 0; j < 4; j++)
                #pragma unroll
                for (int v = 0; v < 4; v++) acc[g][mt][j][v] = 0.f;

    auto load_stage = [&](int stage, int ch) {
        const uint32_t off = stage * STG_B;
        const __half* a = gA + ch * BK;
        const __half* b = gB + ch * BK;
        #pragma unroll
        for (int i = 0; i < 2; i++)
            asm volatile("cp.async.cg.shared.global [%0], [%1], 16;\n"
                         :: "r"(sA + off + i * 64 * RP * 2), "l"(a + (size_t)i * 64 * IDIM));
        #pragma unroll
        for (int i = 0; i < 3; i++)
            asm volatile("cp.async.cg.shared.global [%0], [%1], 16;\n"
                         :: "r"(sB + off + i * 64 * RP * 2), "l"(b + (size_t)i * 64 * IDIM));
        asm volatile("cp.async.commit_group;\n");
    };

    load_stage(0, 0);
    load_stage(1, 1);
    load_stage(2, 2);

    // ldmatrix lane offsets
    const int a_row = lane & 15;
    const int a_k8  = (lane >> 4) * 8;                    // halves
    const int b_row = (lane & 7) + ((lane >> 4) << 3);    // n within 16
    const int b_k8  = ((lane >> 3) & 1) * 8;              // halves

    for (int kt = 0; kt < NCH; kt++) {
        asm volatile("cp.async.wait_group %0;\n" :: "n"(NST - 2));
        __syncthreads();
        const int cur = kt % NST;
        if (kt + 3 < NCH) load_stage((kt + 3) % NST, kt + 3);

        const uint32_t aB = base + cur * STG_B;
        const uint32_t bB = aB + A_H * 2;

        #pragma unroll
        for (int ks = 0; ks < BK / 16; ks++) {
            uint32_t afr[2][4];
            #pragma unroll
            for (int mt = 0; mt < 2; mt++)
                LDMX4(afr[mt], aB + (uint32_t)((wm + mt * 16 + a_row) * RP + ks * 16 + a_k8) * 2);

            uint32_t bfr[2][4][2];
            // preload gate 0 fragments
            #pragma unroll
            for (int nt2 = 0; nt2 < 2; nt2++) {
                uint32_t r[4];
                LDMX4(r, bB + (uint32_t)((0 * 64 + wn + nt2 * 16 + b_row) * RP + ks * 16 + b_k8) * 2);
                bfr[0][nt2 * 2][0] = r[0]; bfr[0][nt2 * 2][1] = r[1];
                bfr[0][nt2 * 2 + 1][0] = r[2]; bfr[0][nt2 * 2 + 1][1] = r[3];
            }
            #pragma unroll
            for (int g = 0; g < 3; g++) {
                if (g < 2) {
                    #pragma unroll
                    for (int nt2 = 0; nt2 < 2; nt2++) {
                        uint32_t r[4];
                        LDMX4(r, bB + (uint32_t)(((g + 1) * 64 + wn + nt2 * 16 + b_row) * RP + ks * 16 + b_k8) * 2);
                        bfr[(g + 1) & 1][nt2 * 2][0] = r[0]; bfr[(g + 1) & 1][nt2 * 2][1] = r[1];
                        bfr[(g + 1) & 1][nt2 * 2 + 1][0] = r[2]; bfr[(g + 1) & 1][nt2 * 2 + 1][1] = r[3];
                    }
                }
                #pragma unroll
                for (int mt = 0; mt < 2; mt++)
                    #pragma unroll
                    for (int j = 0; j < 4; j++)
                        mma16816(acc[g][mt][j], afr[mt], bfr[g & 1][j]);
            }
        }
    }
    __syncthreads();   // done with smem tiles; reuse for transpose staging

    // ---- epilogue: gates + cell + tanh, staged transpose ----
    float* trans = (float*)dsm;          // [64][132]
    float* hlast = out + (size_t)HDIM * BT;
    float* clast = hlast + (size_t)BDIM * HDIM;
    const int grp = lane >> 2, tig = lane & 3;

    #pragma unroll
    for (int mt = 0; mt < 2; mt++) {
        #pragma unroll
        for (int j = 0; j < 4; j++) {
            #pragma unroll
            for (int v = 0; v < 4; v++) {
                const int m_l = wm + mt * 16 + grp + ((v >> 1) << 3);
                const int h_l = wn + j * 8 + tig * 2 + (v & 1);
                const int mg = m0 + m_l;
                const int b = mg & 63, t = mg >> 6;
                const int h = n0 + h_l;
                const int bh = (b << 10) + h;
                const float pf = acc[0][mt][j][v] + g_hr[0][bh];
                const float pi = acc[1][mt][j][v] + g_hr[1][bh];
                const float pg = acc[2][mt][j][v] + g_hr[2][bh];
                const float f  = sigmoid_f(pf);
                const float ii = sigmoid_f(pi);
                const float gg = tanh_f(pg);
                const float cv = f * c0[bh] + ii * gg;
                const float hh = tanh_f(cv);
                trans[h_l * 132 + m_l] = hh;
                if (write_last && t == TDIM - 1) { hlast[bh] = hh; clast[bh] = cv; }
            }
        }
    }
    __syncthreads();
    // vectorized writeback: 64 rows x 128 cols, float4 per thread-step
    #pragma unroll
    for (int idx = tid; idx < 64 * 32; idx += 256) {
        const int h = idx >> 5, m4 = (idx & 31) * 4;
        const float* tr = &trans[h * 132 + m4];
        float4 v = make_float4(tr[0], tr[1], tr[2], tr[3]);
        *(float4*)&out[(size_t)(n0 + h) * BT + (m0 + m4)] = v;
    }
}

// ---------------- launch ----------------
extern "C" void kernel_launch(void* const* d_in, const int* in_sizes, int n_in,
                              void* d_out, int out_size) {
    const float* x   = (const float*)d_in[0];
    const float* h0  = (const float*)d_in[1];
    const float* c0  = (const float*)d_in[2];
    const float* Wf  = (const float*)d_in[3];
    const float* bf  = (const float*)d_in[4];
    const float* Rf  = (const float*)d_in[5];
    const float* rbf = (const float*)d_in[6];
    const float* Wi  = (const float*)d_in[7];
    const float* bi  = (const float*)d_in[8];
    const float* Ri  = (const float*)d_in[9];
    const float* rbi = (const float*)d_in[10];
    const float* Wg  = (const float*)d_in[11];
    const float* bg  = (const float*)d_in[12];
    const float* Rg  = (const float*)d_in[13];
    const float* rbg = (const float*)d_in[14];
    float* out = (float*)d_out;

    cudaFuncSetAttribute(lstm_fused, cudaFuncAttributeMaxDynamicSharedMemorySize, SMEM_DYN);

    // convert inputs to fp16 (x remapped to m'=t*B+b; W packed per n-tile)
    conv_x<<<(int)(((size_t)BT * IDIM / 8) / 256), 256>>>(x);
    conv_w<<<(int)(((size_t)3 * HDIM * IDIM / 8) / 256), 256>>>(Wf, Wi, Wg);

    // recurrent contribution (+ biases), fp32
    hr_kernel<<<(3 * BDIM * HDIM) / 8, 256>>>(h0, Rf, bf, rbf, Ri, bi, rbi, Rg, bg, rbg);

    // fused 3-gate GEMM + epilogue
    const long long need = (long long)HDIM * BT + 2LL * BDIM * HDIM;
    int write_last = ((long long)out_size >= need) ? 1 : 0;
    dim3 grid(HDIM / 64, BT / BM);   // (16, 256); x-fast => A tile reused across n-blocks in L2
    lstm_fused<<<grid, 256, SMEM_DYN>>>(c0, out, write_last);
}